// round 17
// baseline (speedup 1.0000x reference)
#include <cuda_runtime.h>
#include <cuda_fp16.h>
#include <math.h>

#define N_NODES 100000
#define N_EDGES 3200000
#define D_FEAT  128
#define HIDDEN  16
#define NCLS    8
#define CAP     128          // padded CSR row capacity (P(deg>=128) ~ e^-81)

// ---- device scratch (allocation-free contract) ----
__device__ int    g_cnt[N_NODES];            // in-degree; reset by k_g2fin
__device__ int    g_csrc[N_NODES * CAP];     // padded CSR: src ids, row = node*CAP
__device__ float  g_dis[N_NODES];            // deg^-1/2 incl self-loop
__device__ uint2  g_hn1h[N_NODES * 4];       // x@W1 fp16 (unnorm, then *dis in k_norm)
__device__ uint2  g_hn2h[N_NODES * 2];       // (h@W2)*dis fp16

// host-side stream/events for fork-join overlap (no device memory)
static cudaStream_t g_s2;
static cudaEvent_t  g_ev_fork, g_ev_join;
namespace {
struct _Init {
    _Init() {
        cudaStreamCreateWithFlags(&g_s2, cudaStreamNonBlocking);
        cudaEventCreateWithFlags(&g_ev_fork, cudaEventDisableTiming);
        cudaEventCreateWithFlags(&g_ev_join, cudaEventDisableTiming);
    }
};
static _Init _init;
}

// ---- packed f32x2 helpers (sm_103a packed-FP32 pipe; PTX-only) ----
__device__ __forceinline__ unsigned long long pk2(float a, float b) {
    unsigned long long r;
    asm("mov.b64 %0, {%1,%2};" : "=l"(r) : "f"(a), "f"(b));
    return r;
}
__device__ __forceinline__ float2 upk2(unsigned long long v) {
    float2 f;
    asm("mov.b64 {%0,%1}, %2;" : "=f"(f.x), "=f"(f.y) : "l"(v));
    return f;
}
#define ADDX2(acc, v) asm("add.rn.f32x2 %0, %0, %1;" : "+l"(acc) : "l"(v))

// cache-global 8B load (L2-cached, no L1 allocation) for random gathers
__device__ __forceinline__ uint2 ldcg_u2(const uint2* p) {
    uint2 u;
    asm("ld.global.cg.v2.u32 {%0,%1}, [%2];" : "=r"(u.x), "=r"(u.y) : "l"(p));
    return u;
}

// convert packed 4×fp16 (uint2) -> two packed f32x2
__device__ __forceinline__ void h4_to_x2(uint2 u, unsigned long long& v01,
                                         unsigned long long& v23) {
    float2 fa = __half22float2(*reinterpret_cast<__half2*>(&u.x));
    float2 fb = __half22float2(*reinterpret_cast<__half2*>(&u.y));
    v01 = pk2(fa.x, fa.y);
    v23 = pk2(fb.x, fb.y);
}

__device__ __forceinline__ uint2 f4_to_h4(float a, float b, float c, float d) {
    __half2 lo = __floats2half2_rn(a, b);
    __half2 hi = __floats2half2_rn(c, d);
    uint2 u;
    u.x = *reinterpret_cast<unsigned*>(&lo);
    u.y = *reinterpret_cast<unsigned*>(&hi);
    return u;
}

__device__ __forceinline__ float4 h4_to_f4(uint2 u) {
    float2 fa = __half22float2(*reinterpret_cast<__half2*>(&u.x));
    float2 fb = __half22float2(*reinterpret_cast<__half2*>(&u.y));
    return make_float4(fa.x, fa.y, fb.x, fb.y);
}

// ---- single edge pass: count degree AND fill padded CSR (one atomic/edge) ----
__global__ void k_fillpad(const int* __restrict__ ei) {
    int t = blockIdx.x * blockDim.x + threadIdx.x;
    if (t < N_EDGES / 2) {
        int2 s = ((const int2*)ei)[t];
        int2 d = ((const int2*)(ei + N_EDGES))[t];
        int r0 = atomicAdd(&g_cnt[d.x], 1);
        int r1 = atomicAdd(&g_cnt[d.y], 1);
        if (r0 < CAP) g_csrc[d.x * CAP + r0] = s.x;
        if (r1 < CAP) g_csrc[d.y * CAP + r1] = s.y;
    }
}

// ---------------- layer 1 GEMM (UNNORMALIZED): hn1u = fp16(x @ W1) ----------------
__global__ void __launch_bounds__(128) k_gemm1(const float* __restrict__ x,
                                               const float* __restrict__ W1) {
    __shared__ float4 sW[D_FEAT * 4];  // 128 x 16 floats
    int tid = threadIdx.x;
    for (int t = tid; t < D_FEAT * 4; t += blockDim.x)
        sW[t] = ((const float4*)W1)[t];
    __syncthreads();

    int pair = blockIdx.x * blockDim.x + tid;
    int iA = pair * 2;               // N_NODES even -> iA+1 valid
    if (iA >= N_NODES) return;
    int iB = iA + 1;

    float accA[HIDDEN], accB[HIDDEN];
#pragma unroll
    for (int j = 0; j < HIDDEN; j++) { accA[j] = 0.0f; accB[j] = 0.0f; }

    const float4* xa = (const float4*)x + (size_t)iA * (D_FEAT / 4);
    const float4* xb = xa + (D_FEAT / 4);
#pragma unroll 2
    for (int k4 = 0; k4 < D_FEAT / 4; k4++) {
        float4 va = xa[k4];
        float4 vb = xb[k4];
        float xkA[4] = {va.x, va.y, va.z, va.w};
        float xkB[4] = {vb.x, vb.y, vb.z, vb.w};
#pragma unroll
        for (int t = 0; t < 4; t++) {
            int k = k4 * 4 + t;
#pragma unroll
            for (int c = 0; c < 4; c++) {
                float4 w = sW[k * 4 + c];
                accA[c*4+0] = fmaf(xkA[t], w.x, accA[c*4+0]);
                accA[c*4+1] = fmaf(xkA[t], w.y, accA[c*4+1]);
                accA[c*4+2] = fmaf(xkA[t], w.z, accA[c*4+2]);
                accA[c*4+3] = fmaf(xkA[t], w.w, accA[c*4+3]);
                accB[c*4+0] = fmaf(xkB[t], w.x, accB[c*4+0]);
                accB[c*4+1] = fmaf(xkB[t], w.y, accB[c*4+1]);
                accB[c*4+2] = fmaf(xkB[t], w.z, accB[c*4+2]);
                accB[c*4+3] = fmaf(xkB[t], w.w, accB[c*4+3]);
            }
        }
    }

#pragma unroll
    for (int q = 0; q < 4; q++) {
        g_hn1h[iA * 4 + q] = f4_to_h4(accA[q*4+0], accA[q*4+1], accA[q*4+2], accA[q*4+3]);
        g_hn1h[iB * 4 + q] = f4_to_h4(accB[q*4+0], accB[q*4+1], accB[q*4+2], accB[q*4+3]);
    }
}

// ---- normalize: dis = rsqrt(cnt+1); hn1h *= dis (in-place, fp32 math) ----
__global__ void k_norm() {
    int i = blockIdx.x * blockDim.x + threadIdx.x;
    if (i >= N_NODES) return;
    float dis = rsqrtf((float)(g_cnt[i] + 1));
    g_dis[i] = dis;
#pragma unroll
    for (int q = 0; q < 4; q++) {
        float4 v = h4_to_f4(g_hn1h[i * 4 + q]);
        g_hn1h[i * 4 + q] = f4_to_h4(v.x * dis, v.y * dis, v.z * dis, v.w * dis);
    }
}

// ==== fused gather1 + layer2 ==== (4 threads/node; .cg fp16 gather, f32x2 accum)
__global__ void k_g1l2(const float* __restrict__ W2, const float* __restrict__ b1) {
    __shared__ float sW2[HIDDEN * NCLS];
    __shared__ float sb1[HIDDEN];
    int tid = threadIdx.x;
    if (tid < HIDDEN * NCLS) sW2[tid] = W2[tid];
    if (tid < HIDDEN)        sb1[tid] = b1[tid];
    __syncthreads();

    int gidx = blockIdx.x * blockDim.x + tid;
    int node = gidx >> 2;
    bool valid = (node < N_NODES);
    if (!valid) node = N_NODES - 1;
    int lane = tid & 31;
    int q = lane & 3;
    unsigned gmask = 0xFu << (lane & ~3);   // this 4-lane group

    int cnt = min(g_cnt[node], CAP);
    int beg = node * CAP;

    unsigned long long a01, a23;
    h4_to_x2(g_hn1h[node * 4 + q], a01, a23);   // self-loop term

    int nblk = cnt >> 3;
    for (int k = 0; k < nblk; k++) {
        // group loads 8 ids: lane q reads csrc[beg+8k+2q .. +1]  (32B = 1 sector)
        uint2 c = *(const uint2*)&g_csrc[beg + k * 8 + q * 2];
#pragma unroll
        for (int j = 0; j < 8; j++) {
            int sj = __shfl_sync(gmask, (j & 1) ? (int)c.y : (int)c.x, j >> 1, 4);
            unsigned long long v01, v23;
            h4_to_x2(ldcg_u2(&g_hn1h[sj * 4 + q]), v01, v23);
            ADDX2(a01, v01);
            ADDX2(a23, v23);
        }
    }
    for (int e = beg + (cnt & ~7); e < beg + cnt; e++) {
        int s = __ldg(&g_csrc[e]);
        unsigned long long v01, v23;
        h4_to_x2(ldcg_u2(&g_hn1h[s * 4 + q]), v01, v23);
        ADDX2(a01, v01);
        ADDX2(a23, v23);
    }

    float2 f01 = upk2(a01);
    float2 f23 = upk2(a23);
    float dis = g_dis[node];
    float h[4];
    h[0] = fmaxf(fmaf(dis, f01.x, sb1[q * 4 + 0]), 0.0f);
    h[1] = fmaxf(fmaf(dis, f01.y, sb1[q * 4 + 1]), 0.0f);
    h[2] = fmaxf(fmaf(dis, f23.x, sb1[q * 4 + 2]), 0.0f);
    h[3] = fmaxf(fmaf(dis, f23.y, sb1[q * 4 + 3]), 0.0f);

    float o[NCLS];
#pragma unroll
    for (int c = 0; c < NCLS; c++) o[c] = 0.0f;
#pragma unroll
    for (int t = 0; t < 4; t++) {
        const float* wr = &sW2[(q * 4 + t) * NCLS];
#pragma unroll
        for (int c = 0; c < NCLS; c++) o[c] = fmaf(h[t], wr[c], o[c]);
    }
#pragma unroll
    for (int c = 0; c < NCLS; c++) {
        o[c] += __shfl_xor_sync(0xffffffffu, o[c], 1);
        o[c] += __shfl_xor_sync(0xffffffffu, o[c], 2);
    }
    if (valid && q < 2)
        g_hn2h[node * 2 + q] = f4_to_h4(o[q*4+0]*dis, o[q*4+1]*dis,
                                        o[q*4+2]*dis, o[q*4+3]*dis);
}

// ==== fused gather2 + log_softmax ==== (2 threads/node); resets g_cnt
__global__ void k_g2fin(const float* __restrict__ b2, float* __restrict__ out) {
    int tid = threadIdx.x;
    int gidx = blockIdx.x * blockDim.x + tid;
    int node = gidx >> 1;
    bool valid = (node < N_NODES);
    if (!valid) node = N_NODES - 1;
    int lane = tid & 31;
    int q2 = lane & 1;
    unsigned gmask = 0x3u << (lane & ~1);   // this 2-lane group

    int cnt = min(g_cnt[node], CAP);
    int beg = node * CAP;

    unsigned long long a01, a23;
    h4_to_x2(g_hn2h[node * 2 + q2], a01, a23);   // self-loop term

    int nblk = cnt >> 3;
    for (int k = 0; k < nblk; k++) {
        // group loads 8 ids: lane q2 reads csrc[beg+8k+4*q2 .. +3]
        uint4 c = *(const uint4*)&g_csrc[beg + k * 8 + q2 * 4];
#pragma unroll
        for (int j = 0; j < 8; j++) {
            int comp = j & 3;
            int srcv = (comp == 0) ? (int)c.x : (comp == 1) ? (int)c.y
                     : (comp == 2) ? (int)c.z : (int)c.w;
            int sj = __shfl_sync(gmask, srcv, j >> 2, 2);
            unsigned long long v01, v23;
            h4_to_x2(ldcg_u2(&g_hn2h[sj * 2 + q2]), v01, v23);
            ADDX2(a01, v01);
            ADDX2(a23, v23);
        }
    }
    for (int e = beg + (cnt & ~7); e < beg + cnt; e++) {
        int s = __ldg(&g_csrc[e]);
        unsigned long long v01, v23;
        h4_to_x2(ldcg_u2(&g_hn2h[s * 2 + q2]), v01, v23);
        ADDX2(a01, v01);
        ADDX2(a23, v23);
    }

    float2 f01 = upk2(a01);
    float2 f23 = upk2(a23);
    float dis = g_dis[node];
    float mine[4];
    mine[0] = fmaf(dis, f01.x, __ldg(&b2[q2 * 4 + 0]));
    mine[1] = fmaf(dis, f01.y, __ldg(&b2[q2 * 4 + 1]));
    mine[2] = fmaf(dis, f23.x, __ldg(&b2[q2 * 4 + 2]));
    mine[3] = fmaf(dis, f23.y, __ldg(&b2[q2 * 4 + 3]));

    float other[4];
#pragma unroll
    for (int t = 0; t < 4; t++)
        other[t] = __shfl_xor_sync(0xffffffffu, mine[t], 1);

    float l[NCLS];
#pragma unroll
    for (int t = 0; t < 4; t++) { l[q2*4+t] = mine[t]; l[(1-q2)*4+t] = other[t]; }

    float m = l[0];
#pragma unroll
    for (int c = 1; c < NCLS; c++) m = fmaxf(m, l[c]);
    float s = 0.0f;
#pragma unroll
    for (int c = 0; c < NCLS; c++) s += expf(l[c] - m);
    float lse = m + logf(s);

    if (valid) {
        float4* op = (float4*)(out + (size_t)node * NCLS);
        op[q2] = make_float4(mine[0]-lse, mine[1]-lse, mine[2]-lse, mine[3]-lse);
        if (q2 == 0) g_cnt[node] = 0;   // reset degree counter for next call
    }
}

extern "C" void kernel_launch(void* const* d_in, const int* in_sizes, int n_in,
                              void* d_out, int out_size) {
    const float* x  = (const float*)d_in[0];
    const int*   ei = (const int*)d_in[1];     // int32 (JAX x64 disabled)
    const float* W1 = (const float*)d_in[2];
    const float* b1 = (const float*)d_in[3];
    const float* W2 = (const float*)d_in[4];
    const float* b2 = (const float*)d_in[5];
    float* out = (float*)d_out;

    const int NB_NODE = (N_NODES + 255) / 256;
    const int NB_FILL = (N_EDGES / 2 + 255) / 256;
    const int NB_G1   = (N_NODES * 4 + 255) / 256;
    const int NB_G2   = (N_NODES * 2 + 255) / 256;
    const int NB_GEMM = (N_NODES / 2 + 127) / 128;

    // fork at t=0: gemm1 (FMA/L1, no deps) || fillpad (L2-atomic edge pass)
    cudaEventRecord(g_ev_fork, 0);
    cudaStreamWaitEvent(g_s2, g_ev_fork, 0);
    k_gemm1 <<<NB_GEMM, 128, 0, g_s2>>>(x, W1);    // launch 1
    cudaEventRecord(g_ev_join, g_s2);

    k_fillpad <<<NB_FILL, 256>>>(ei);              // launch 2

    cudaStreamWaitEvent(0, g_ev_join, 0);
    k_norm  <<<NB_NODE, 256>>>();                  // launch 3
    k_g1l2  <<<NB_G1,   256>>>(W2, b1);            // launch 4 -> profiled
    k_g2fin <<<NB_G2,   256>>>(b2, out);           // launch 5
}